// round 1
// baseline (speedup 1.0000x reference)
#include <cuda_runtime.h>
#include <math.h>

#define Ee 768
#define Hh 12
#define Dd 64
#define Bb 8
#define Nn 1024
#define Mtot (Bb * Nn)   // 8192

// Scratch (static device globals; allocation is forbidden)
__device__ float g_q[(size_t)Mtot * Ee];
__device__ float g_k[(size_t)Mtot * Ee];
__device__ float g_v[(size_t)Mtot * Ee];
__device__ float g_attn[(size_t)Mtot * Ee];

// ---------------------------------------------------------------------------
// C = (A * W^T + bias) * scale
// A: M x K row-major, W: N x K row-major (torch-style (out,in)), C: M x N
// Tiles: BM=BN=128, BK=8, 256 threads, 8x8 register blocking per thread.
// All dims (8192, 768) divide evenly -> no bounds checks.
// ---------------------------------------------------------------------------
__global__ __launch_bounds__(256)
void sgemm_wt_bias(const float* __restrict__ A,
                   const float* __restrict__ W,
                   const float* __restrict__ bias,
                   float* __restrict__ C,
                   int M, int Nc, int K, float scale)
{
    const int BM = 128, BN = 128, BK = 8;
    __shared__ float As[BK][BM];
    __shared__ float Ws[BK][BN];

    int tid = threadIdx.x;
    int tx = tid & 15;        // 0..15  -> col group
    int ty = tid >> 4;        // 0..15  -> row group
    int rowBase = blockIdx.y * BM;
    int colBase = blockIdx.x * BN;

    int loadRow = tid >> 1;          // 0..127
    int loadK   = (tid & 1) * 4;     // 0 or 4

    float acc[8][8];
    #pragma unroll
    for (int i = 0; i < 8; i++)
        #pragma unroll
        for (int j = 0; j < 8; j++) acc[i][j] = 0.f;

    const float* Arow = A + (size_t)(rowBase + loadRow) * K + loadK;
    const float* Wrow = W + (size_t)(colBase + loadRow) * K + loadK;

    for (int k0 = 0; k0 < K; k0 += BK) {
        float4 av = *(const float4*)(Arow + k0);
        float4 wv = *(const float4*)(Wrow + k0);
        As[loadK + 0][loadRow] = av.x;
        As[loadK + 1][loadRow] = av.y;
        As[loadK + 2][loadRow] = av.z;
        As[loadK + 3][loadRow] = av.w;
        Ws[loadK + 0][loadRow] = wv.x;
        Ws[loadK + 1][loadRow] = wv.y;
        Ws[loadK + 2][loadRow] = wv.z;
        Ws[loadK + 3][loadRow] = wv.w;
        __syncthreads();

        #pragma unroll
        for (int kk = 0; kk < BK; kk++) {
            float a[8], b[8];
            *(float4*)&a[0] = *(const float4*)&As[kk][ty * 8];
            *(float4*)&a[4] = *(const float4*)&As[kk][ty * 8 + 4];
            *(float4*)&b[0] = *(const float4*)&Ws[kk][tx * 8];
            *(float4*)&b[4] = *(const float4*)&Ws[kk][tx * 8 + 4];
            #pragma unroll
            for (int i = 0; i < 8; i++)
                #pragma unroll
                for (int j = 0; j < 8; j++)
                    acc[i][j] += a[i] * b[j];
        }
        __syncthreads();
    }

    float bb[8];
    #pragma unroll
    for (int j = 0; j < 8; j++) bb[j] = bias[colBase + tx * 8 + j];

    #pragma unroll
    for (int i = 0; i < 8; i++) {
        float* crow = C + (size_t)(rowBase + ty * 8 + i) * Nc + colBase + tx * 8;
        float4 w0, w1;
        w0.x = (acc[i][0] + bb[0]) * scale;
        w0.y = (acc[i][1] + bb[1]) * scale;
        w0.z = (acc[i][2] + bb[2]) * scale;
        w0.w = (acc[i][3] + bb[3]) * scale;
        w1.x = (acc[i][4] + bb[4]) * scale;
        w1.y = (acc[i][5] + bb[5]) * scale;
        w1.z = (acc[i][6] + bb[6]) * scale;
        w1.w = (acc[i][7] + bb[7]) * scale;
        *(float4*)&crow[0] = w0;
        *(float4*)&crow[4] = w1;
    }
}

// ---------------------------------------------------------------------------
// Fused flash attention (fp32, with dense additive bias from gmem).
// Block = (qtile 64 rows, head h, batch b). 256 threads.
// Never materializes the (B,H,N,N) score tensor.
// Smem: Qd (Q transposed [d][r]), KP (K transposed [d][c] then reused as
// P transposed [c][r]), Vs (V natural [k][d]) = exactly 48KB.
// ---------------------------------------------------------------------------
__global__ __launch_bounds__(256)
void attn_flash(const float* __restrict__ abias)
{
    __shared__ float Qd[64][64];
    __shared__ float KP[64][64];
    __shared__ float Vs[64][64];

    int tid = threadIdx.x;
    int tx = tid & 15;
    int ty = tid >> 4;
    int qt = blockIdx.x;
    int h  = blockIdx.y;
    int b  = blockIdx.z;
    int q0 = qt * 64;

    const float* qg = g_q + ((size_t)b * Nn + q0) * Ee + h * Dd;
    const float* kg = g_k + ((size_t)b * Nn) * Ee + h * Dd;
    const float* vg = g_v + ((size_t)b * Nn) * Ee + h * Dd;
    const float* bg = abias + (((size_t)b * Hh + h) * Nn + q0) * Nn;

    // Load Q tile transposed: Qd[d][r]
    for (int i = tid; i < 64 * 16; i += 256) {
        int r = i >> 4;
        int c4 = (i & 15) * 4;
        float4 v = *(const float4*)&qg[(size_t)r * Ee + c4];
        Qd[c4 + 0][r] = v.x;
        Qd[c4 + 1][r] = v.y;
        Qd[c4 + 2][r] = v.z;
        Qd[c4 + 3][r] = v.w;
    }

    float o[4][4];
    float m_i[4], l_i[4];
    #pragma unroll
    for (int i = 0; i < 4; i++) {
        m_i[i] = -1e30f;
        l_i[i] = 0.f;
        #pragma unroll
        for (int j = 0; j < 4; j++) o[i][j] = 0.f;
    }

    for (int kt = 0; kt < Nn / 64; kt++) {
        int k0 = kt * 64;
        __syncthreads();   // guards KP/Vs reuse from previous iter + Q load (first iter)

        // Load K transposed (KP[d][c]) and V natural (Vs[k][d])
        for (int i = tid; i < 64 * 16; i += 256) {
            int r = i >> 4;
            int c4 = (i & 15) * 4;
            float4 kv = *(const float4*)&kg[(size_t)(k0 + r) * Ee + c4];
            KP[c4 + 0][r] = kv.x;
            KP[c4 + 1][r] = kv.y;
            KP[c4 + 2][r] = kv.z;
            KP[c4 + 3][r] = kv.w;
            *(float4*)&Vs[r][c4] = *(const float4*)&vg[(size_t)(k0 + r) * Ee + c4];
        }
        __syncthreads();

        // S = Q K^T + bias  (q already scaled by d^-0.5 in projection)
        float s[4][4];
        #pragma unroll
        for (int i = 0; i < 4; i++) {
            float4 bv = *(const float4*)&bg[(size_t)(ty * 4 + i) * Nn + k0 + tx * 4];
            s[i][0] = bv.x; s[i][1] = bv.y; s[i][2] = bv.z; s[i][3] = bv.w;
        }
        #pragma unroll 16
        for (int d = 0; d < 64; d++) {
            float4 a = *(const float4*)&Qd[d][ty * 4];
            float4 kk = *(const float4*)&KP[d][tx * 4];
            float av[4] = {a.x, a.y, a.z, a.w};
            float bv[4] = {kk.x, kk.y, kk.z, kk.w};
            #pragma unroll
            for (int i = 0; i < 4; i++)
                #pragma unroll
                for (int j = 0; j < 4; j++)
                    s[i][j] += av[i] * bv[j];
        }
        __syncthreads();   // all reads of KP-as-K done before overwriting with P

        // Online softmax update (per-row stats replicated across the 16 tx lanes)
        #pragma unroll
        for (int i = 0; i < 4; i++) {
            float mx = fmaxf(fmaxf(s[i][0], s[i][1]), fmaxf(s[i][2], s[i][3]));
            #pragma unroll
            for (int w = 1; w < 16; w <<= 1)
                mx = fmaxf(mx, __shfl_xor_sync(0xffffffffu, mx, w));
            float m_new = fmaxf(m_i[i], mx);
            float alpha = __expf(m_i[i] - m_new);
            float ps = 0.f;
            #pragma unroll
            for (int j = 0; j < 4; j++) {
                s[i][j] = __expf(s[i][j] - m_new);
                ps += s[i][j];
            }
            #pragma unroll
            for (int w = 1; w < 16; w <<= 1)
                ps += __shfl_xor_sync(0xffffffffu, ps, w);
            l_i[i] = l_i[i] * alpha + ps;
            m_i[i] = m_new;
            #pragma unroll
            for (int j = 0; j < 4; j++) o[i][j] *= alpha;
        }

        // Store P transposed into KP: KP[c][r]
        #pragma unroll
        for (int i = 0; i < 4; i++)
            #pragma unroll
            for (int j = 0; j < 4; j++)
                KP[tx * 4 + j][ty * 4 + i] = s[i][j];
        __syncthreads();

        // O += P V : o[i][j] covers rows ty*4+i, d-cols tx*4+j
        #pragma unroll 16
        for (int kk = 0; kk < 64; kk++) {
            float4 p = *(const float4*)&KP[kk][ty * 4];
            float4 vv = *(const float4*)&Vs[kk][tx * 4];
            float pv[4] = {p.x, p.y, p.z, p.w};
            float vw[4] = {vv.x, vv.y, vv.z, vv.w};
            #pragma unroll
            for (int i = 0; i < 4; i++)
                #pragma unroll
                for (int j = 0; j < 4; j++)
                    o[i][j] += pv[i] * vw[j];
        }
    }

    // Normalize and write back (b, n, e) layout
    float* og = g_attn + ((size_t)b * Nn + q0) * Ee + h * Dd;
    #pragma unroll
    for (int i = 0; i < 4; i++) {
        float inv = 1.f / l_i[i];
        float4 w;
        w.x = o[i][0] * inv;
        w.y = o[i][1] * inv;
        w.z = o[i][2] * inv;
        w.w = o[i][3] * inv;
        *(float4*)&og[(size_t)(ty * 4 + i) * Ee + tx * 4] = w;
    }
}

// ---------------------------------------------------------------------------
extern "C" void kernel_launch(void* const* d_in, const int* in_sizes, int n_in,
                              void* d_out, int out_size)
{
    const float* query = (const float*)d_in[0];
    const float* abias = (const float*)d_in[1];
    const float* Wq = (const float*)d_in[2];
    const float* bq = (const float*)d_in[3];
    const float* Wk = (const float*)d_in[4];
    const float* bk = (const float*)d_in[5];
    const float* Wv = (const float*)d_in[6];
    const float* bv = (const float*)d_in[7];
    const float* Wo = (const float*)d_in[8];
    const float* bo = (const float*)d_in[9];
    float* out = (float*)d_out;

    float* gq; cudaGetSymbolAddress((void**)&gq, g_q);
    float* gk; cudaGetSymbolAddress((void**)&gk, g_k);
    float* gv; cudaGetSymbolAddress((void**)&gv, g_v);
    float* ga; cudaGetSymbolAddress((void**)&ga, g_attn);

    const float scaling = 0.125f;  // Dd^-0.5 = 64^-0.5

    dim3 gThreads(256);
    dim3 gGridProj(Ee / 128, Mtot / 128);   // (6, 64)

    // QKV projections (q pre-scaled)
    sgemm_wt_bias<<<gGridProj, gThreads>>>(query, Wq, bq, gq, Mtot, Ee, Ee, scaling);
    sgemm_wt_bias<<<gGridProj, gThreads>>>(query, Wk, bk, gk, Mtot, Ee, Ee, 1.0f);
    sgemm_wt_bias<<<gGridProj, gThreads>>>(query, Wv, bv, gv, Mtot, Ee, Ee, 1.0f);

    // Fused flash attention with bias
    dim3 aGrid(Nn / 64, Hh, Bb);            // (16, 12, 8)
    attn_flash<<<aGrid, gThreads>>>(abias);

    // Output projection -> d_out
    sgemm_wt_bias<<<gGridProj, gThreads>>>(ga, Wo, bo, out, Mtot, Ee, Ee, 1.0f);
}

// round 3
// speedup vs baseline: 1.5982x; 1.5982x over previous
#include <cuda_runtime.h>
#include <cstdint>
#include <math.h>

#define Ee 768
#define Hh 12
#define Dd 64
#define Bb 8
#define Nn 1024
#define Mtot (Bb * Nn)   // 8192

// Scratch (static device globals; allocation is forbidden)
__device__ float g_q[(size_t)Mtot * Ee];
__device__ float g_k[(size_t)Mtot * Ee];
__device__ float g_v[(size_t)Mtot * Ee];
__device__ float g_attn[(size_t)Mtot * Ee];

// ======================= mma.sync helpers ==================================
__device__ __forceinline__ uint32_t f2tf32(float f) {
    uint32_t r;
    asm("cvt.rna.tf32.f32 %0, %1;" : "=r"(r) : "f"(f));
    return r;
}

// D(16x8) += A(16x8) * B(8x8);  A row-major frag (4 regs), B col-major frag (2 regs)
__device__ __forceinline__ void mma_tf32(float* d, const uint32_t* a, const uint32_t* b) {
    asm volatile(
        "mma.sync.aligned.m16n8k8.row.col.f32.tf32.tf32.f32 "
        "{%0,%1,%2,%3}, {%4,%5,%6,%7}, {%8,%9}, {%0,%1,%2,%3};"
        : "+f"(d[0]), "+f"(d[1]), "+f"(d[2]), "+f"(d[3])
        : "r"(a[0]), "r"(a[1]), "r"(a[2]), "r"(a[3]), "r"(b[0]), "r"(b[1]));
}

// ======================= tf32 tensor-core GEMM =============================
// C[M,Nc] = (A[M,K] @ W[Nc,K]^T + bias) * scale   (torch-style weights)
// CTA 128x128, BK=16, 256 threads (8 warps as 2 rows x 4 cols, warp = 64x32).
#define BM 128
#define BN 128
#define BKt 16
#define PITCH 20   // floats; (20m + k) % 32 distinct over a warp's frag lanes

__global__ __launch_bounds__(256)
void gemm_mma(const float* __restrict__ A, const float* __restrict__ W,
              const float* __restrict__ bias, float* __restrict__ C,
              int M, int Nc, int K, float scale)
{
    __shared__ float As[2][BM][PITCH];
    __shared__ float Bs[2][BN][PITCH];

    const int tid  = threadIdx.x;
    const int lane = tid & 31;
    const int w    = tid >> 5;
    const int wr   = w & 1;        // warp row: 0..1 (64 rows each)
    const int wc   = w >> 1;       // warp col: 0..3 (32 cols each)
    const int rowBase = blockIdx.y * BM;
    const int colBase = blockIdx.x * BN;

    float acc[4][4][4];
    #pragma unroll
    for (int i = 0; i < 4; i++)
        #pragma unroll
        for (int j = 0; j < 4; j++)
            #pragma unroll
            for (int q = 0; q < 4; q++) acc[i][j][q] = 0.f;

    // Loader mapping: thread -> (row lm0 / lm0+64, k-quad lkq)
    const int lm0 = tid >> 2;          // 0..63
    const int lkq = (tid & 3) * 4;     // 0,4,8,12

    const float* Ag0 = A + (size_t)(rowBase + lm0)      * K + lkq;
    const float* Ag1 = A + (size_t)(rowBase + lm0 + 64) * K + lkq;
    const float* Wg0 = W + (size_t)(colBase + lm0)      * K + lkq;
    const float* Wg1 = W + (size_t)(colBase + lm0 + 64) * K + lkq;

    float4 ra0, ra1, rb0, rb1;

    const int NSTEP = K / BKt;   // 48

    // prologue: tile 0 -> regs -> smem buf0 ; tile 1 -> regs
    ra0 = *(const float4*)(Ag0);
    ra1 = *(const float4*)(Ag1);
    rb0 = *(const float4*)(Wg0);
    rb1 = *(const float4*)(Wg1);
    {
        As[0][lm0     ][lkq + 0] = __uint_as_float(f2tf32(ra0.x));
        As[0][lm0     ][lkq + 1] = __uint_as_float(f2tf32(ra0.y));
        As[0][lm0     ][lkq + 2] = __uint_as_float(f2tf32(ra0.z));
        As[0][lm0     ][lkq + 3] = __uint_as_float(f2tf32(ra0.w));
        As[0][lm0 + 64][lkq + 0] = __uint_as_float(f2tf32(ra1.x));
        As[0][lm0 + 64][lkq + 1] = __uint_as_float(f2tf32(ra1.y));
        As[0][lm0 + 64][lkq + 2] = __uint_as_float(f2tf32(ra1.z));
        As[0][lm0 + 64][lkq + 3] = __uint_as_float(f2tf32(ra1.w));
        Bs[0][lm0     ][lkq + 0] = __uint_as_float(f2tf32(rb0.x));
        Bs[0][lm0     ][lkq + 1] = __uint_as_float(f2tf32(rb0.y));
        Bs[0][lm0     ][lkq + 2] = __uint_as_float(f2tf32(rb0.z));
        Bs[0][lm0     ][lkq + 3] = __uint_as_float(f2tf32(rb0.w));
        Bs[0][lm0 + 64][lkq + 0] = __uint_as_float(f2tf32(rb1.x));
        Bs[0][lm0 + 64][lkq + 1] = __uint_as_float(f2tf32(rb1.y));
        Bs[0][lm0 + 64][lkq + 2] = __uint_as_float(f2tf32(rb1.z));
        Bs[0][lm0 + 64][lkq + 3] = __uint_as_float(f2tf32(rb1.w));
    }
    ra0 = *(const float4*)(Ag0 + BKt);
    ra1 = *(const float4*)(Ag1 + BKt);
    rb0 = *(const float4*)(Wg0 + BKt);
    rb1 = *(const float4*)(Wg1 + BKt);

    const int mrow = wr * 64 + (lane >> 2);   // base row for frags
    const int ncol = wc * 32 + (lane >> 2);   // base col for frags
    const int klo  = lane & 3;

    for (int c = 0; c < NSTEP; c++) {
        __syncthreads();
        int cur = c & 1, nxt = cur ^ 1;

        // stage tile c+1 regs -> smem[nxt]
        if (c + 1 < NSTEP) {
            As[nxt][lm0     ][lkq + 0] = __uint_as_float(f2tf32(ra0.x));
            As[nxt][lm0     ][lkq + 1] = __uint_as_float(f2tf32(ra0.y));
            As[nxt][lm0     ][lkq + 2] = __uint_as_float(f2tf32(ra0.z));
            As[nxt][lm0     ][lkq + 3] = __uint_as_float(f2tf32(ra0.w));
            As[nxt][lm0 + 64][lkq + 0] = __uint_as_float(f2tf32(ra1.x));
            As[nxt][lm0 + 64][lkq + 1] = __uint_as_float(f2tf32(ra1.y));
            As[nxt][lm0 + 64][lkq + 2] = __uint_as_float(f2tf32(ra1.z));
            As[nxt][lm0 + 64][lkq + 3] = __uint_as_float(f2tf32(ra1.w));
            Bs[nxt][lm0     ][lkq + 0] = __uint_as_float(f2tf32(rb0.x));
            Bs[nxt][lm0     ][lkq + 1] = __uint_as_float(f2tf32(rb0.y));
            Bs[nxt][lm0     ][lkq + 2] = __uint_as_float(f2tf32(rb0.z));
            Bs[nxt][lm0     ][lkq + 3] = __uint_as_float(f2tf32(rb0.w));
            Bs[nxt][lm0 + 64][lkq + 0] = __uint_as_float(f2tf32(rb1.x));
            Bs[nxt][lm0 + 64][lkq + 1] = __uint_as_float(f2tf32(rb1.y));
            Bs[nxt][lm0 + 64][lkq + 2] = __uint_as_float(f2tf32(rb1.z));
            Bs[nxt][lm0 + 64][lkq + 3] = __uint_as_float(f2tf32(rb1.w));
        }
        // issue global loads for tile c+2
        if (c + 2 < NSTEP) {
            int off = (c + 2) * BKt;
            ra0 = *(const float4*)(Ag0 + off);
            ra1 = *(const float4*)(Ag1 + off);
            rb0 = *(const float4*)(Wg0 + off);
            rb1 = *(const float4*)(Wg1 + off);
        }

        // compute on smem[cur]: two k8 sub-steps
        #pragma unroll
        for (int ks = 0; ks < BKt; ks += 8) {
            uint32_t af[4][4], bf[4][2];
            #pragma unroll
            for (int mf = 0; mf < 4; mf++) {
                af[mf][0] = __float_as_uint(As[cur][mrow + mf * 16    ][ks + klo]);
                af[mf][1] = __float_as_uint(As[cur][mrow + mf * 16 + 8][ks + klo]);
                af[mf][2] = __float_as_uint(As[cur][mrow + mf * 16    ][ks + klo + 4]);
                af[mf][3] = __float_as_uint(As[cur][mrow + mf * 16 + 8][ks + klo + 4]);
            }
            #pragma unroll
            for (int nf = 0; nf < 4; nf++) {
                bf[nf][0] = __float_as_uint(Bs[cur][ncol + nf * 8][ks + klo]);
                bf[nf][1] = __float_as_uint(Bs[cur][ncol + nf * 8][ks + klo + 4]);
            }
            #pragma unroll
            for (int mf = 0; mf < 4; mf++)
                #pragma unroll
                for (int nf = 0; nf < 4; nf++)
                    mma_tf32(acc[mf][nf], af[mf], bf[nf]);
        }
    }

    // Epilogue: bias + scale; c0,c1 at (r, 2q),(r,2q+1); c2,c3 at (r+8, ...)
    #pragma unroll
    for (int mf = 0; mf < 4; mf++) {
        int r0 = rowBase + wr * 64 + mf * 16 + (lane >> 2);
        #pragma unroll
        for (int nf = 0; nf < 4; nf++) {
            int c0 = colBase + wc * 32 + nf * 8 + (lane & 3) * 2;
            float b0 = bias[c0], b1 = bias[c0 + 1];
            float2 lo, hi;
            lo.x = (acc[mf][nf][0] + b0) * scale;
            lo.y = (acc[mf][nf][1] + b1) * scale;
            hi.x = (acc[mf][nf][2] + b0) * scale;
            hi.y = (acc[mf][nf][3] + b1) * scale;
            *(float2*)&C[(size_t)r0 * Nc + c0]       = lo;
            *(float2*)&C[(size_t)(r0 + 8) * Nc + c0] = hi;
        }
    }
}

// ---------------------------------------------------------------------------
// Fused flash attention (fp32, with dense additive bias from gmem). Unchanged.
// ---------------------------------------------------------------------------
__global__ __launch_bounds__(256)
void attn_flash(const float* __restrict__ abias)
{
    __shared__ float Qd[64][64];
    __shared__ float KP[64][64];
    __shared__ float Vs[64][64];

    int tid = threadIdx.x;
    int tx = tid & 15;
    int ty = tid >> 4;
    int qt = blockIdx.x;
    int h  = blockIdx.y;
    int b  = blockIdx.z;
    int q0 = qt * 64;

    const float* qg = g_q + ((size_t)b * Nn + q0) * Ee + h * Dd;
    const float* kg = g_k + ((size_t)b * Nn) * Ee + h * Dd;
    const float* vg = g_v + ((size_t)b * Nn) * Ee + h * Dd;
    const float* bg = abias + (((size_t)b * Hh + h) * Nn + q0) * Nn;

    for (int i = tid; i < 64 * 16; i += 256) {
        int r = i >> 4;
        int c4 = (i & 15) * 4;
        float4 v = *(const float4*)&qg[(size_t)r * Ee + c4];
        Qd[c4 + 0][r] = v.x;
        Qd[c4 + 1][r] = v.y;
        Qd[c4 + 2][r] = v.z;
        Qd[c4 + 3][r] = v.w;
    }

    float o[4][4];
    float m_i[4], l_i[4];
    #pragma unroll
    for (int i = 0; i < 4; i++) {
        m_i[i] = -1e30f;
        l_i[i] = 0.f;
        #pragma unroll
        for (int j = 0; j < 4; j++) o[i][j] = 0.f;
    }

    for (int kt = 0; kt < Nn / 64; kt++) {
        int k0 = kt * 64;
        __syncthreads();

        for (int i = tid; i < 64 * 16; i += 256) {
            int r = i >> 4;
            int c4 = (i & 15) * 4;
            float4 kv = *(const float4*)&kg[(size_t)(k0 + r) * Ee + c4];
            KP[c4 + 0][r] = kv.x;
            KP[c4 + 1][r] = kv.y;
            KP[c4 + 2][r] = kv.z;
            KP[c4 + 3][r] = kv.w;
            *(float4*)&Vs[r][c4] = *(const float4*)&vg[(size_t)(k0 + r) * Ee + c4];
        }
        __syncthreads();

        float s[4][4];
        #pragma unroll
        for (int i = 0; i < 4; i++) {
            float4 bv = *(const float4*)&bg[(size_t)(ty * 4 + i) * Nn + k0 + tx * 4];
            s[i][0] = bv.x; s[i][1] = bv.y; s[i][2] = bv.z; s[i][3] = bv.w;
        }
        #pragma unroll 16
        for (int d = 0; d < 64; d++) {
            float4 a = *(const float4*)&Qd[d][ty * 4];
            float4 kk = *(const float4*)&KP[d][tx * 4];
            float av[4] = {a.x, a.y, a.z, a.w};
            float bv[4] = {kk.x, kk.y, kk.z, kk.w};
            #pragma unroll
            for (int i = 0; i < 4; i++)
                #pragma unroll
                for (int j = 0; j < 4; j++)
                    s[i][j] += av[i] * bv[j];
        }
        __syncthreads();

        #pragma unroll
        for (int i = 0; i < 4; i++) {
            float mx = fmaxf(fmaxf(s[i][0], s[i][1]), fmaxf(s[i][2], s[i][3]));
            #pragma unroll
            for (int w = 1; w < 16; w <<= 1)
                mx = fmaxf(mx, __shfl_xor_sync(0xffffffffu, mx, w));
            float m_new = fmaxf(m_i[i], mx);
            float alpha = __expf(m_i[i] - m_new);
            float ps = 0.f;
            #pragma unroll
            for (int j = 0; j < 4; j++) {
                s[i][j] = __expf(s[i][j] - m_new);
                ps += s[i][j];
            }
            #pragma unroll
            for (int w = 1; w < 16; w <<= 1)
                ps += __shfl_xor_sync(0xffffffffu, ps, w);
            l_i[i] = l_i[i] * alpha + ps;
            m_i[i] = m_new;
            #pragma unroll
            for (int j = 0; j < 4; j++) o[i][j] *= alpha;
        }

        #pragma unroll
        for (int i = 0; i < 4; i++)
            #pragma unroll
            for (int j = 0; j < 4; j++)
                KP[tx * 4 + j][ty * 4 + i] = s[i][j];
        __syncthreads();

        #pragma unroll 16
        for (int kk = 0; kk < 64; kk++) {
            float4 p = *(const float4*)&KP[kk][ty * 4];
            float4 vv = *(const float4*)&Vs[kk][tx * 4];
            float pv[4] = {p.x, p.y, p.z, p.w};
            float vw[4] = {vv.x, vv.y, vv.z, vv.w};
            #pragma unroll
            for (int i = 0; i < 4; i++)
                #pragma unroll
                for (int j = 0; j < 4; j++)
                    o[i][j] += pv[i] * vw[j];
        }
    }

    float* og = g_attn + ((size_t)b * Nn + q0) * Ee + h * Dd;
    #pragma unroll
    for (int i = 0; i < 4; i++) {
        float inv = 1.f / l_i[i];
        float4 w;
        w.x = o[i][0] * inv;
        w.y = o[i][1] * inv;
        w.z = o[i][2] * inv;
        w.w = o[i][3] * inv;
        *(float4*)&og[(size_t)(ty * 4 + i) * Ee + tx * 4] = w;
    }
}

// ---------------------------------------------------------------------------
extern "C" void kernel_launch(void* const* d_in, const int* in_sizes, int n_in,
                              void* d_out, int out_size)
{
    const float* query = (const float*)d_in[0];
    const float* abias = (const float*)d_in[1];
    const float* Wq = (const float*)d_in[2];
    const float* bq = (const float*)d_in[3];
    const float* Wk = (const float*)d_in[4];
    const float* bk = (const float*)d_in[5];
    const float* Wv = (const float*)d_in[6];
    const float* bv = (const float*)d_in[7];
    const float* Wo = (const float*)d_in[8];
    const float* bo = (const float*)d_in[9];
    float* out = (float*)d_out;

    float* gq; cudaGetSymbolAddress((void**)&gq, g_q);
    float* gk; cudaGetSymbolAddress((void**)&gk, g_k);
    float* gv; cudaGetSymbolAddress((void**)&gv, g_v);
    float* ga; cudaGetSymbolAddress((void**)&ga, g_attn);

    const float scaling = 0.125f;  // Dd^-0.5

    dim3 gThreads(256);
    dim3 gGridProj(Ee / BN, Mtot / BM);     // (6, 64)

    gemm_mma<<<gGridProj, gThreads>>>(query, Wq, bq, gq, Mtot, Ee, Ee, scaling);
    gemm_mma<<<gGridProj, gThreads>>>(query, Wk, bk, gk, Mtot, Ee, Ee, 1.0f);
    gemm_mma<<<gGridProj, gThreads>>>(query, Wv, bv, gv, Mtot, Ee, Ee, 1.0f);

    dim3 aGrid(Nn / 64, Hh, Bb);            // (16, 12, 8)
    attn_flash<<<aGrid, gThreads>>>(abias);

    gemm_mma<<<gGridProj, gThreads>>>(ga, Wo, bo, out, Mtot, Ee, Ee, 1.0f);
}

// round 5
// speedup vs baseline: 1.7623x; 1.1026x over previous
#include <cuda_runtime.h>
#include <cstdint>
#include <math.h>

#define Ee 768
#define Hh 12
#define Dd 64
#define Bb 8
#define Nn 1024
#define Mtot (Bb * Nn)   // 8192

// Scratch (static device globals; allocation is forbidden)
__device__ float g_q[(size_t)Mtot * Ee];
__device__ float g_k[(size_t)Mtot * Ee];
__device__ float g_v[(size_t)Mtot * Ee];
__device__ float g_attn[(size_t)Mtot * Ee];

// ======================= mma.sync helpers ==================================
__device__ __forceinline__ uint32_t f2tf32(float f) {
    uint32_t r;
    asm("cvt.rna.tf32.f32 %0, %1;" : "=r"(r) : "f"(f));
    return r;
}

__device__ __forceinline__ void mma_tf32(float* d, const uint32_t* a, const uint32_t* b) {
    asm volatile(
        "mma.sync.aligned.m16n8k8.row.col.f32.tf32.tf32.f32 "
        "{%0,%1,%2,%3}, {%4,%5,%6,%7}, {%8,%9}, {%0,%1,%2,%3};"
        : "+f"(d[0]), "+f"(d[1]), "+f"(d[2]), "+f"(d[3])
        : "r"(a[0]), "r"(a[1]), "r"(a[2]), "r"(a[3]), "r"(b[0]), "r"(b[1]));
}

// ======================= tf32 tensor-core GEMM =============================
// C[M,Nc] = (A[M,K] @ W[Nc,K]^T + bias) * scale   (torch-style weights)
#define BM 128
#define BN 128
#define BKt 16
#define PITCH 20

__global__ __launch_bounds__(256)
void gemm_mma(const float* __restrict__ A, const float* __restrict__ W,
              const float* __restrict__ bias, float* __restrict__ C,
              int M, int Nc, int K, float scale)
{
    __shared__ float As[2][BM][PITCH];
    __shared__ float Bs[2][BN][PITCH];

    const int tid  = threadIdx.x;
    const int lane = tid & 31;
    const int w    = tid >> 5;
    const int wr   = w & 1;
    const int wc   = w >> 1;
    const int rowBase = blockIdx.y * BM;
    const int colBase = blockIdx.x * BN;

    float acc[4][4][4];
    #pragma unroll
    for (int i = 0; i < 4; i++)
        #pragma unroll
        for (int j = 0; j < 4; j++)
            #pragma unroll
            for (int q = 0; q < 4; q++) acc[i][j][q] = 0.f;

    const int lm0 = tid >> 2;
    const int lkq = (tid & 3) * 4;

    const float* Ag0 = A + (size_t)(rowBase + lm0)      * K + lkq;
    const float* Ag1 = A + (size_t)(rowBase + lm0 + 64) * K + lkq;
    const float* Wg0 = W + (size_t)(colBase + lm0)      * K + lkq;
    const float* Wg1 = W + (size_t)(colBase + lm0 + 64) * K + lkq;

    float4 ra0, ra1, rb0, rb1;
    const int NSTEP = K / BKt;

    ra0 = *(const float4*)(Ag0);
    ra1 = *(const float4*)(Ag1);
    rb0 = *(const float4*)(Wg0);
    rb1 = *(const float4*)(Wg1);
    {
        As[0][lm0     ][lkq + 0] = __uint_as_float(f2tf32(ra0.x));
        As[0][lm0     ][lkq + 1] = __uint_as_float(f2tf32(ra0.y));
        As[0][lm0     ][lkq + 2] = __uint_as_float(f2tf32(ra0.z));
        As[0][lm0     ][lkq + 3] = __uint_as_float(f2tf32(ra0.w));
        As[0][lm0 + 64][lkq + 0] = __uint_as_float(f2tf32(ra1.x));
        As[0][lm0 + 64][lkq + 1] = __uint_as_float(f2tf32(ra1.y));
        As[0][lm0 + 64][lkq + 2] = __uint_as_float(f2tf32(ra1.z));
        As[0][lm0 + 64][lkq + 3] = __uint_as_float(f2tf32(ra1.w));
        Bs[0][lm0     ][lkq + 0] = __uint_as_float(f2tf32(rb0.x));
        Bs[0][lm0     ][lkq + 1] = __uint_as_float(f2tf32(rb0.y));
        Bs[0][lm0     ][lkq + 2] = __uint_as_float(f2tf32(rb0.z));
        Bs[0][lm0     ][lkq + 3] = __uint_as_float(f2tf32(rb0.w));
        Bs[0][lm0 + 64][lkq + 0] = __uint_as_float(f2tf32(rb1.x));
        Bs[0][lm0 + 64][lkq + 1] = __uint_as_float(f2tf32(rb1.y));
        Bs[0][lm0 + 64][lkq + 2] = __uint_as_float(f2tf32(rb1.z));
        Bs[0][lm0 + 64][lkq + 3] = __uint_as_float(f2tf32(rb1.w));
    }
    ra0 = *(const float4*)(Ag0 + BKt);
    ra1 = *(const float4*)(Ag1 + BKt);
    rb0 = *(const float4*)(Wg0 + BKt);
    rb1 = *(const float4*)(Wg1 + BKt);

    const int mrow = wr * 64 + (lane >> 2);
    const int ncol = wc * 32 + (lane >> 2);
    const int klo  = lane & 3;

    for (int c = 0; c < NSTEP; c++) {
        __syncthreads();
        int cur = c & 1, nxt = cur ^ 1;

        if (c + 1 < NSTEP) {
            As[nxt][lm0     ][lkq + 0] = __uint_as_float(f2tf32(ra0.x));
            As[nxt][lm0     ][lkq + 1] = __uint_as_float(f2tf32(ra0.y));
            As[nxt][lm0     ][lkq + 2] = __uint_as_float(f2tf32(ra0.z));
            As[nxt][lm0     ][lkq + 3] = __uint_as_float(f2tf32(ra0.w));
            As[nxt][lm0 + 64][lkq + 0] = __uint_as_float(f2tf32(ra1.x));
            As[nxt][lm0 + 64][lkq + 1] = __uint_as_float(f2tf32(ra1.y));
            As[nxt][lm0 + 64][lkq + 2] = __uint_as_float(f2tf32(ra1.z));
            As[nxt][lm0 + 64][lkq + 3] = __uint_as_float(f2tf32(ra1.w));
            Bs[nxt][lm0     ][lkq + 0] = __uint_as_float(f2tf32(rb0.x));
            Bs[nxt][lm0     ][lkq + 1] = __uint_as_float(f2tf32(rb0.y));
            Bs[nxt][lm0     ][lkq + 2] = __uint_as_float(f2tf32(rb0.z));
            Bs[nxt][lm0     ][lkq + 3] = __uint_as_float(f2tf32(rb0.w));
            Bs[nxt][lm0 + 64][lkq + 0] = __uint_as_float(f2tf32(rb1.x));
            Bs[nxt][lm0 + 64][lkq + 1] = __uint_as_float(f2tf32(rb1.y));
            Bs[nxt][lm0 + 64][lkq + 2] = __uint_as_float(f2tf32(rb1.z));
            Bs[nxt][lm0 + 64][lkq + 3] = __uint_as_float(f2tf32(rb1.w));
        }
        if (c + 2 < NSTEP) {
            int off = (c + 2) * BKt;
            ra0 = *(const float4*)(Ag0 + off);
            ra1 = *(const float4*)(Ag1 + off);
            rb0 = *(const float4*)(Wg0 + off);
            rb1 = *(const float4*)(Wg1 + off);
        }

        #pragma unroll
        for (int ks = 0; ks < BKt; ks += 8) {
            uint32_t af[4][4], bf[4][2];
            #pragma unroll
            for (int mf = 0; mf < 4; mf++) {
                af[mf][0] = __float_as_uint(As[cur][mrow + mf * 16    ][ks + klo]);
                af[mf][1] = __float_as_uint(As[cur][mrow + mf * 16 + 8][ks + klo]);
                af[mf][2] = __float_as_uint(As[cur][mrow + mf * 16    ][ks + klo + 4]);
                af[mf][3] = __float_as_uint(As[cur][mrow + mf * 16 + 8][ks + klo + 4]);
            }
            #pragma unroll
            for (int nf = 0; nf < 4; nf++) {
                bf[nf][0] = __float_as_uint(Bs[cur][ncol + nf * 8][ks + klo]);
                bf[nf][1] = __float_as_uint(Bs[cur][ncol + nf * 8][ks + klo + 4]);
            }
            #pragma unroll
            for (int mf = 0; mf < 4; mf++)
                #pragma unroll
                for (int nf = 0; nf < 4; nf++)
                    mma_tf32(acc[mf][nf], af[mf], bf[nf]);
        }
    }

    #pragma unroll
    for (int mf = 0; mf < 4; mf++) {
        int r0 = rowBase + wr * 64 + mf * 16 + (lane >> 2);
        #pragma unroll
        for (int nf = 0; nf < 4; nf++) {
            int c0 = colBase + wc * 32 + nf * 8 + (lane & 3) * 2;
            float b0 = bias[c0], b1 = bias[c0 + 1];
            float2 lo, hi;
            lo.x = (acc[mf][nf][0] + b0) * scale;
            lo.y = (acc[mf][nf][1] + b1) * scale;
            hi.x = (acc[mf][nf][2] + b0) * scale;
            hi.y = (acc[mf][nf][3] + b1) * scale;
            *(float2*)&C[(size_t)r0 * Nc + c0]       = lo;
            *(float2*)&C[(size_t)(r0 + 8) * Nc + c0] = hi;
        }
    }
}

// ---------------------------------------------------------------------------
// Flash attention v2 (fp32): q-tile 64, k-tile 128, 256 threads (16x16),
// S-frag 4x8, O-frag 4x4. Smem (dynamic, 84KB), all pitches = 0 mod 4:
//   Qd [64][68]   : Q transposed (d-major)
//   KP [64][132]  : K transposed [d][k] in S phase; P row-major [q][k] in PV
//   Vs [128][64]  : V natural
// ---------------------------------------------------------------------------
#define QD_PITCH 68
#define KP_PITCH 132
#define QD_OFF   0
#define KP_OFF   (64 * QD_PITCH)                 // 4352
#define VS_OFF   (KP_OFF + 64 * KP_PITCH)        // 4352 + 8448 = 12800
#define ATTN_SMEM ((VS_OFF + 128 * 64) * 4)      // (12800 + 8192)*4 = 83968 B

__global__ __launch_bounds__(256)
void attn_flash2(const float* __restrict__ abias)
{
    extern __shared__ float sm[];
    float* Qd = sm + QD_OFF;
    float* KP = sm + KP_OFF;
    float* Vs = sm + VS_OFF;

    const int tid = threadIdx.x;
    const int tx = tid & 15;
    const int ty = tid >> 4;
    const int q0 = blockIdx.x * 64;
    const int h  = blockIdx.y;
    const int b  = blockIdx.z;

    const float* qg = g_q + ((size_t)b * Nn + q0) * Ee + h * Dd;
    const float* kg = g_k + (size_t)b * Nn * Ee + h * Dd;
    const float* vg = g_v + (size_t)b * Nn * Ee + h * Dd;
    const float* bg = abias + (((size_t)b * Hh + h) * Nn + q0) * Nn;

    // Load Q tile transposed: Qd[d][q]
    #pragma unroll
    for (int it = 0; it < 4; it++) {
        int idx = tid + it * 256;          // 0..1023
        int r = idx >> 4;                  // q row 0..63
        int d4 = (idx & 15) * 4;
        float4 v = *(const float4*)&qg[(size_t)r * Ee + d4];
        Qd[(d4 + 0) * QD_PITCH + r] = v.x;
        Qd[(d4 + 1) * QD_PITCH + r] = v.y;
        Qd[(d4 + 2) * QD_PITCH + r] = v.z;
        Qd[(d4 + 3) * QD_PITCH + r] = v.w;
    }

    float o[4][4];
    float m_i[4], l_i[4];
    #pragma unroll
    for (int i = 0; i < 4; i++) {
        m_i[i] = -1e30f;
        l_i[i] = 0.f;
        #pragma unroll
        for (int j = 0; j < 4; j++) o[i][j] = 0.f;
    }

    for (int kt = 0; kt < Nn / 128; kt++) {
        const int k0 = kt * 128;
        __syncthreads();   // prior P/Vs reads done; also covers Q load on iter 0

        // Load K transposed (KP[d][k]) and V natural (Vs[k][d])
        #pragma unroll
        for (int it = 0; it < 8; it++) {
            int idx = tid + it * 256;      // 0..2047
            int r = idx >> 4;              // k row 0..127
            int d4 = (idx & 15) * 4;
            float4 kv = *(const float4*)&kg[(size_t)(k0 + r) * Ee + d4];
            KP[(d4 + 0) * KP_PITCH + r] = kv.x;
            KP[(d4 + 1) * KP_PITCH + r] = kv.y;
            KP[(d4 + 2) * KP_PITCH + r] = kv.z;
            KP[(d4 + 3) * KP_PITCH + r] = kv.w;
            *(float4*)&Vs[r * 64 + d4] = *(const float4*)&vg[(size_t)(k0 + r) * Ee + d4];
        }
        __syncthreads();

        // S = Q K^T + bias (q pre-scaled)
        float s[4][8];
        #pragma unroll
        for (int i = 0; i < 4; i++) {
            const float* brow = bg + (size_t)(ty * 4 + i) * Nn + k0 + tx * 8;
            float4 b0 = *(const float4*)&brow[0];
            float4 b1 = *(const float4*)&brow[4];
            s[i][0] = b0.x; s[i][1] = b0.y; s[i][2] = b0.z; s[i][3] = b0.w;
            s[i][4] = b1.x; s[i][5] = b1.y; s[i][6] = b1.z; s[i][7] = b1.w;
        }
        #pragma unroll 8
        for (int d = 0; d < 64; d++) {
            float4 aq  = *(const float4*)&Qd[d * QD_PITCH + ty * 4];
            float4 k0v = *(const float4*)&KP[d * KP_PITCH + tx * 8];
            float4 k1v = *(const float4*)&KP[d * KP_PITCH + tx * 8 + 4];
            float av[4] = {aq.x, aq.y, aq.z, aq.w};
            float bv[8] = {k0v.x, k0v.y, k0v.z, k0v.w, k1v.x, k1v.y, k1v.z, k1v.w};
            #pragma unroll
            for (int i = 0; i < 4; i++)
                #pragma unroll
                for (int j = 0; j < 8; j++)
                    s[i][j] += av[i] * bv[j];
        }

        // Online softmax (row stats across the 16 tx lanes)
        #pragma unroll
        for (int i = 0; i < 4; i++) {
            float mx = s[i][0];
            #pragma unroll
            for (int j = 1; j < 8; j++) mx = fmaxf(mx, s[i][j]);
            #pragma unroll
            for (int w = 1; w < 16; w <<= 1)
                mx = fmaxf(mx, __shfl_xor_sync(0xffffffffu, mx, w));
            float m_new = fmaxf(m_i[i], mx);
            float alpha = __expf(m_i[i] - m_new);
            float ps = 0.f;
            #pragma unroll
            for (int j = 0; j < 8; j++) {
                s[i][j] = __expf(s[i][j] - m_new);
                ps += s[i][j];
            }
            #pragma unroll
            for (int w = 1; w < 16; w <<= 1)
                ps += __shfl_xor_sync(0xffffffffu, ps, w);
            l_i[i] = l_i[i] * alpha + ps;
            m_i[i] = m_new;
            #pragma unroll
            for (int j = 0; j < 4; j++) o[i][j] *= alpha;
        }

        __syncthreads();   // all KP (K) reads done before overwrite with P

        // Store P row-major: P[q][k] into KP[64][132]
        #pragma unroll
        for (int i = 0; i < 4; i++) {
            float4 p0, p1;
            p0.x = s[i][0]; p0.y = s[i][1]; p0.z = s[i][2]; p0.w = s[i][3];
            p1.x = s[i][4]; p1.y = s[i][5]; p1.z = s[i][6]; p1.w = s[i][7];
            *(float4*)&KP[(ty * 4 + i) * KP_PITCH + tx * 8]     = p0;
            *(float4*)&KP[(ty * 4 + i) * KP_PITCH + tx * 8 + 4] = p1;
        }
        __syncthreads();

        // O += P V, k in steps of 4
        #pragma unroll 4
        for (int kk0 = 0; kk0 < 128; kk0 += 4) {
            float4 pk[4], vv[4];
            #pragma unroll
            for (int i = 0; i < 4; i++)
                pk[i] = *(const float4*)&KP[(ty * 4 + i) * KP_PITCH + kk0];
            #pragma unroll
            for (int kk = 0; kk < 4; kk++)
                vv[kk] = *(const float4*)&Vs[(kk0 + kk) * 64 + tx * 4];
            float pr[4][4] = {
                {pk[0].x, pk[0].y, pk[0].z, pk[0].w},
                {pk[1].x, pk[1].y, pk[1].z, pk[1].w},
                {pk[2].x, pk[2].y, pk[2].z, pk[2].w},
                {pk[3].x, pk[3].y, pk[3].z, pk[3].w}};
            float vr[4][4] = {
                {vv[0].x, vv[0].y, vv[0].z, vv[0].w},
                {vv[1].x, vv[1].y, vv[1].z, vv[1].w},
                {vv[2].x, vv[2].y, vv[2].z, vv[2].w},
                {vv[3].x, vv[3].y, vv[3].z, vv[3].w}};
            #pragma unroll
            for (int i = 0; i < 4; i++)
                #pragma unroll
                for (int kk = 0; kk < 4; kk++)
                    #pragma unroll
                    for (int j = 0; j < 4; j++)
                        o[i][j] += pr[i][kk] * vr[kk][j];
        }
    }

    // Normalize and write back (b, n, e) layout
    float* og = g_attn + ((size_t)b * Nn + q0) * Ee + h * Dd;
    #pragma unroll
    for (int i = 0; i < 4; i++) {
        float inv = 1.f / l_i[i];
        float4 w;
        w.x = o[i][0] * inv;
        w.y = o[i][1] * inv;
        w.z = o[i][2] * inv;
        w.w = o[i][3] * inv;
        *(float4*)&og[(size_t)(ty * 4 + i) * Ee + tx * 4] = w;
    }
}

// ---------------------------------------------------------------------------
extern "C" void kernel_launch(void* const* d_in, const int* in_sizes, int n_in,
                              void* d_out, int out_size)
{
    const float* query = (const float*)d_in[0];
    const float* abias = (const float*)d_in[1];
    const float* Wq = (const float*)d_in[2];
    const float* bq = (const float*)d_in[3];
    const float* Wk = (const float*)d_in[4];
    const float* bk = (const float*)d_in[5];
    const float* Wv = (const float*)d_in[6];
    const float* bv = (const float*)d_in[7];
    const float* Wo = (const float*)d_in[8];
    const float* bo = (const float*)d_in[9];
    float* out = (float*)d_out;

    float* gq; cudaGetSymbolAddress((void**)&gq, g_q);
    float* gk; cudaGetSymbolAddress((void**)&gk, g_k);
    float* gv; cudaGetSymbolAddress((void**)&gv, g_v);
    float* ga; cudaGetSymbolAddress((void**)&ga, g_attn);

    cudaFuncSetAttribute(attn_flash2, cudaFuncAttributeMaxDynamicSharedMemorySize, ATTN_SMEM);

    const float scaling = 0.125f;  // Dd^-0.5

    dim3 gThreads(256);
    dim3 gGridProj(Ee / BN, Mtot / BM);     // (6, 64)

    gemm_mma<<<gGridProj, gThreads>>>(query, Wq, bq, gq, Mtot, Ee, Ee, scaling);
    gemm_mma<<<gGridProj, gThreads>>>(query, Wk, bk, gk, Mtot, Ee, Ee, 1.0f);
    gemm_mma<<<gGridProj, gThreads>>>(query, Wv, bv, gv, Mtot, Ee, Ee, 1.0f);

    dim3 aGrid(Nn / 64, Hh, Bb);            // (16, 12, 8)
    attn_flash2<<<aGrid, gThreads, ATTN_SMEM>>>(abias);

    gemm_mma<<<gGridProj, gThreads>>>(ga, Wo, bo, out, Mtot, Ee, Ee, 1.0f);
}

// round 6
// speedup vs baseline: 3.2233x; 1.8290x over previous
#include <cuda_runtime.h>
#include <cstdint>
#include <math.h>

#define Ee 768
#define Hh 12
#define Dd 64
#define Bb 8
#define Nn 1024
#define Mtot (Bb * Nn)   // 8192

// Scratch (static device globals; allocation is forbidden)
__device__ float g_q[(size_t)Mtot * Ee];
__device__ float g_k[(size_t)Mtot * Ee];
__device__ float g_v[(size_t)Mtot * Ee];
__device__ float g_attn[(size_t)Mtot * Ee];

// ======================= mma.sync helpers ==================================
__device__ __forceinline__ uint32_t f2tf32(float f) {
    uint32_t r;
    asm("cvt.rna.tf32.f32 %0, %1;" : "=r"(r) : "f"(f));
    return r;
}
__device__ __forceinline__ float f2tf32f(float f) {
    return __uint_as_float(f2tf32(f));
}

__device__ __forceinline__ void mma_tf32(float* d, const uint32_t* a, const uint32_t* b) {
    asm volatile(
        "mma.sync.aligned.m16n8k8.row.col.f32.tf32.tf32.f32 "
        "{%0,%1,%2,%3}, {%4,%5,%6,%7}, {%8,%9}, {%0,%1,%2,%3};"
        : "+f"(d[0]), "+f"(d[1]), "+f"(d[2]), "+f"(d[3])
        : "r"(a[0]), "r"(a[1]), "r"(a[2]), "r"(a[3]), "r"(b[0]), "r"(b[1]));
}

// ======================= tf32 tensor-core GEMM =============================
// C[M,Nc] = (A[M,K] @ W[Nc,K]^T + bias) * scale   (torch-style weights)
#define BM 128
#define BN 128
#define BKt 16
#define PITCH 20

__global__ __launch_bounds__(256)
void gemm_mma(const float* __restrict__ A, const float* __restrict__ W,
              const float* __restrict__ bias, float* __restrict__ C,
              int M, int Nc, int K, float scale)
{
    __shared__ float As[2][BM][PITCH];
    __shared__ float Bs[2][BN][PITCH];

    const int tid  = threadIdx.x;
    const int lane = tid & 31;
    const int w    = tid >> 5;
    const int wr   = w & 1;
    const int wc   = w >> 1;
    const int rowBase = blockIdx.y * BM;
    const int colBase = blockIdx.x * BN;

    float acc[4][4][4];
    #pragma unroll
    for (int i = 0; i < 4; i++)
        #pragma unroll
        for (int j = 0; j < 4; j++)
            #pragma unroll
            for (int q = 0; q < 4; q++) acc[i][j][q] = 0.f;

    const int lm0 = tid >> 2;
    const int lkq = (tid & 3) * 4;

    const float* Ag0 = A + (size_t)(rowBase + lm0)      * K + lkq;
    const float* Ag1 = A + (size_t)(rowBase + lm0 + 64) * K + lkq;
    const float* Wg0 = W + (size_t)(colBase + lm0)      * K + lkq;
    const float* Wg1 = W + (size_t)(colBase + lm0 + 64) * K + lkq;

    float4 ra0, ra1, rb0, rb1;
    const int NSTEP = K / BKt;

    ra0 = *(const float4*)(Ag0);
    ra1 = *(const float4*)(Ag1);
    rb0 = *(const float4*)(Wg0);
    rb1 = *(const float4*)(Wg1);
    {
        As[0][lm0     ][lkq + 0] = f2tf32f(ra0.x);
        As[0][lm0     ][lkq + 1] = f2tf32f(ra0.y);
        As[0][lm0     ][lkq + 2] = f2tf32f(ra0.z);
        As[0][lm0     ][lkq + 3] = f2tf32f(ra0.w);
        As[0][lm0 + 64][lkq + 0] = f2tf32f(ra1.x);
        As[0][lm0 + 64][lkq + 1] = f2tf32f(ra1.y);
        As[0][lm0 + 64][lkq + 2] = f2tf32f(ra1.z);
        As[0][lm0 + 64][lkq + 3] = f2tf32f(ra1.w);
        Bs[0][lm0     ][lkq + 0] = f2tf32f(rb0.x);
        Bs[0][lm0     ][lkq + 1] = f2tf32f(rb0.y);
        Bs[0][lm0     ][lkq + 2] = f2tf32f(rb0.z);
        Bs[0][lm0     ][lkq + 3] = f2tf32f(rb0.w);
        Bs[0][lm0 + 64][lkq + 0] = f2tf32f(rb1.x);
        Bs[0][lm0 + 64][lkq + 1] = f2tf32f(rb1.y);
        Bs[0][lm0 + 64][lkq + 2] = f2tf32f(rb1.z);
        Bs[0][lm0 + 64][lkq + 3] = f2tf32f(rb1.w);
    }
    ra0 = *(const float4*)(Ag0 + BKt);
    ra1 = *(const float4*)(Ag1 + BKt);
    rb0 = *(const float4*)(Wg0 + BKt);
    rb1 = *(const float4*)(Wg1 + BKt);

    const int mrow = wr * 64 + (lane >> 2);
    const int ncol = wc * 32 + (lane >> 2);
    const int klo  = lane & 3;

    for (int c = 0; c < NSTEP; c++) {
        __syncthreads();
        int cur = c & 1, nxt = cur ^ 1;

        if (c + 1 < NSTEP) {
            As[nxt][lm0     ][lkq + 0] = f2tf32f(ra0.x);
            As[nxt][lm0     ][lkq + 1] = f2tf32f(ra0.y);
            As[nxt][lm0     ][lkq + 2] = f2tf32f(ra0.z);
            As[nxt][lm0     ][lkq + 3] = f2tf32f(ra0.w);
            As[nxt][lm0 + 64][lkq + 0] = f2tf32f(ra1.x);
            As[nxt][lm0 + 64][lkq + 1] = f2tf32f(ra1.y);
            As[nxt][lm0 + 64][lkq + 2] = f2tf32f(ra1.z);
            As[nxt][lm0 + 64][lkq + 3] = f2tf32f(ra1.w);
            Bs[nxt][lm0     ][lkq + 0] = f2tf32f(rb0.x);
            Bs[nxt][lm0     ][lkq + 1] = f2tf32f(rb0.y);
            Bs[nxt][lm0     ][lkq + 2] = f2tf32f(rb0.z);
            Bs[nxt][lm0     ][lkq + 3] = f2tf32f(rb0.w);
            Bs[nxt][lm0 + 64][lkq + 0] = f2tf32f(rb1.x);
            Bs[nxt][lm0 + 64][lkq + 1] = f2tf32f(rb1.y);
            Bs[nxt][lm0 + 64][lkq + 2] = f2tf32f(rb1.z);
            Bs[nxt][lm0 + 64][lkq + 3] = f2tf32f(rb1.w);
        }
        if (c + 2 < NSTEP) {
            int off = (c + 2) * BKt;
            ra0 = *(const float4*)(Ag0 + off);
            ra1 = *(const float4*)(Ag1 + off);
            rb0 = *(const float4*)(Wg0 + off);
            rb1 = *(const float4*)(Wg1 + off);
        }

        #pragma unroll
        for (int ks = 0; ks < BKt; ks += 8) {
            uint32_t af[4][4], bf[4][2];
            #pragma unroll
            for (int mf = 0; mf < 4; mf++) {
                af[mf][0] = __float_as_uint(As[cur][mrow + mf * 16    ][ks + klo]);
                af[mf][1] = __float_as_uint(As[cur][mrow + mf * 16 + 8][ks + klo]);
                af[mf][2] = __float_as_uint(As[cur][mrow + mf * 16    ][ks + klo + 4]);
                af[mf][3] = __float_as_uint(As[cur][mrow + mf * 16 + 8][ks + klo + 4]);
            }
            #pragma unroll
            for (int nf = 0; nf < 4; nf++) {
                bf[nf][0] = __float_as_uint(Bs[cur][ncol + nf * 8][ks + klo]);
                bf[nf][1] = __float_as_uint(Bs[cur][ncol + nf * 8][ks + klo + 4]);
            }
            #pragma unroll
            for (int mf = 0; mf < 4; mf++)
                #pragma unroll
                for (int nf = 0; nf < 4; nf++)
                    mma_tf32(acc[mf][nf], af[mf], bf[nf]);
        }
    }

    #pragma unroll
    for (int mf = 0; mf < 4; mf++) {
        int r0 = rowBase + wr * 64 + mf * 16 + (lane >> 2);
        #pragma unroll
        for (int nf = 0; nf < 4; nf++) {
            int c0 = colBase + wc * 32 + nf * 8 + (lane & 3) * 2;
            float b0 = bias[c0], b1 = bias[c0 + 1];
            float2 lo, hi;
            lo.x = (acc[mf][nf][0] + b0) * scale;
            lo.y = (acc[mf][nf][1] + b1) * scale;
            hi.x = (acc[mf][nf][2] + b0) * scale;
            hi.y = (acc[mf][nf][3] + b1) * scale;
            *(float2*)&C[(size_t)r0 * Nc + c0]       = lo;
            *(float2*)&C[(size_t)(r0 + 8) * Nc + c0] = hi;
        }
    }
}

// ---------------------------------------------------------------------------
// Flash attention via mma.sync tf32.
// CTA: 128 q-rows x (h,b); k-tile 64; 8 warps as 4(m) x 2(n); warp tile 32x32.
// Smem (floats): Qs[128][68], KP[128][68] (K then P), Vs[64][72], stats 2x256.
// Bias is loaded straight into the S accumulators (C-frag init).
// ---------------------------------------------------------------------------
#define QP 68                       // pitch for Qs/KP: 68 % 32 == 4 -> 4*lr+lc unique
#define VPIT 72                     // pitch for Vs:   72 % 32 == 8 -> 8*lc+lr unique
#define QS_OFF 0
#define KP_OFF2 (128 * QP)          // 8704
#define VS_OFF2 (KP_OFF2 + 128 * QP)// 17408
#define ST_OFF  (VS_OFF2 + 64 * VPIT) // 22016
#define ATTN_SMEM ((ST_OFF + 512) * 4)  // 90112 bytes

__global__ __launch_bounds__(256)
void attn_mma(const float* __restrict__ abias)
{
    extern __shared__ float sm[];
    float* Qs = sm + QS_OFF;
    float* KP = sm + KP_OFF2;
    float* Vs = sm + VS_OFF2;
    float* stMax = sm + ST_OFF;        // [128][2]
    float* stSum = sm + ST_OFF + 256;  // [128][2]

    const int tid  = threadIdx.x;
    const int lane = tid & 31;
    const int w    = tid >> 5;
    const int ms   = (w & 3) * 32;     // m-strip base (q)
    const int nsi  = w >> 2;           // n-strip index 0/1
    const int ns   = nsi * 32;         // n-strip base
    const int lr   = lane >> 2;        // 0..7
    const int lc   = lane & 3;         // 0..3

    const int q0 = blockIdx.x * 128;
    const int h  = blockIdx.y;
    const int b  = blockIdx.z;

    const float* qg = g_q + ((size_t)b * Nn + q0) * Ee + h * Dd;
    const float* kg = g_k + (size_t)b * Nn * Ee + h * Dd;
    const float* vg = g_v + (size_t)b * Nn * Ee + h * Dd;
    const float* bg = abias + (((size_t)b * Hh + h) * Nn + q0) * Nn;

    // Load Q once (tf32-rounded), row-major [q][d]
    #pragma unroll
    for (int it = 0; it < 8; it++) {
        int idx = tid + it * 256;      // 0..2047
        int r = idx >> 4;              // 0..127
        int c4 = (idx & 15) * 4;
        float4 v = *(const float4*)&qg[(size_t)r * Ee + c4];
        float4 t;
        t.x = f2tf32f(v.x); t.y = f2tf32f(v.y); t.z = f2tf32f(v.z); t.w = f2tf32f(v.w);
        *(float4*)&Qs[r * QP + c4] = t;
    }

    float o[2][4][4];
    float m_i[4], l_i[4];
    #pragma unroll
    for (int r4 = 0; r4 < 4; r4++) { m_i[r4] = -1e30f; l_i[r4] = 0.f; }
    #pragma unroll
    for (int mf = 0; mf < 2; mf++)
        #pragma unroll
        for (int nf = 0; nf < 4; nf++)
            #pragma unroll
            for (int e = 0; e < 4; e++) o[mf][nf][e] = 0.f;

    for (int kt = 0; kt < Nn / 64; kt++) {
        const int k0 = kt * 64;
        __syncthreads();   // prior iter's P/V reads done (and Q fill on iter 0)

        // K tile -> KP[0..63][QP], V tile -> Vs[0..63][VPIT], both tf32-rounded
        #pragma unroll
        for (int it = 0; it < 4; it++) {
            int idx = tid + it * 256;  // 0..1023
            int r = idx >> 4;          // 0..63
            int c4 = (idx & 15) * 4;
            float4 kv = *(const float4*)&kg[(size_t)(k0 + r) * Ee + c4];
            float4 tk;
            tk.x = f2tf32f(kv.x); tk.y = f2tf32f(kv.y); tk.z = f2tf32f(kv.z); tk.w = f2tf32f(kv.w);
            *(float4*)&KP[r * QP + c4] = tk;
            float4 vv = *(const float4*)&vg[(size_t)(k0 + r) * Ee + c4];
            float4 tv;
            tv.x = f2tf32f(vv.x); tv.y = f2tf32f(vv.y); tv.z = f2tf32f(vv.z); tv.w = f2tf32f(vv.w);
            *(float4*)&Vs[r * VPIT + c4] = tv;
        }
        __syncthreads();

        // S accumulators initialized with bias (C-frag layout)
        float c[2][4][4];
        #pragma unroll
        for (int mf = 0; mf < 2; mf++) {
            #pragma unroll
            for (int nf = 0; nf < 4; nf++) {
                const float* bp = bg + (size_t)(ms + 16 * mf + lr) * Nn + k0 + ns + 8 * nf + 2 * lc;
                float2 t0 = *(const float2*)bp;
                float2 t1 = *(const float2*)(bp + 8 * Nn);
                c[mf][nf][0] = t0.x; c[mf][nf][1] = t0.y;
                c[mf][nf][2] = t1.x; c[mf][nf][3] = t1.y;
            }
        }

        // S = Q K^T (+bias already in c)
        #pragma unroll
        for (int ks = 0; ks < 8; ks++) {
            int d0 = ks * 8;
            uint32_t af[2][4], bf[4][2];
            #pragma unroll
            for (int mf = 0; mf < 2; mf++) {
                const float* qp = Qs + (ms + 16 * mf + lr) * QP + d0 + lc;
                af[mf][0] = __float_as_uint(qp[0]);
                af[mf][1] = __float_as_uint(qp[8 * QP]);
                af[mf][2] = __float_as_uint(qp[4]);
                af[mf][3] = __float_as_uint(qp[8 * QP + 4]);
            }
            #pragma unroll
            for (int nf = 0; nf < 4; nf++) {
                const float* kp = KP + (ns + 8 * nf + lr) * QP + d0 + lc;
                bf[nf][0] = __float_as_uint(kp[0]);
                bf[nf][1] = __float_as_uint(kp[4]);
            }
            #pragma unroll
            for (int mf = 0; mf < 2; mf++)
                #pragma unroll
                for (int nf = 0; nf < 4; nf++)
                    mma_tf32(c[mf][nf], af[mf], bf[nf]);
        }

        // Partial row max over this warp's 32 cols
        float pm[4];
        #pragma unroll
        for (int r4 = 0; r4 < 4; r4++) {
            int mf = r4 >> 1, hf = r4 & 1;
            float mx = fmaxf(c[mf][0][2 * hf], c[mf][0][2 * hf + 1]);
            #pragma unroll
            for (int nf = 1; nf < 4; nf++)
                mx = fmaxf(mx, fmaxf(c[mf][nf][2 * hf], c[mf][nf][2 * hf + 1]));
            mx = fmaxf(mx, __shfl_xor_sync(0xffffffffu, mx, 1));
            mx = fmaxf(mx, __shfl_xor_sync(0xffffffffu, mx, 2));
            pm[r4] = mx;
        }
        if (lc == 0) {
            #pragma unroll
            for (int r4 = 0; r4 < 4; r4++)
                stMax[(ms + lr + 8 * r4) * 2 + nsi] = pm[r4];
        }
        __syncthreads();   // also: all warps done with S mma (K reads complete)

        float alpha[4], psum[4];
        #pragma unroll
        for (int r4 = 0; r4 < 4; r4++) {
            float mo = stMax[(ms + lr + 8 * r4) * 2 + (1 - nsi)];
            float mt = fmaxf(pm[r4], mo);
            float mnew = fmaxf(m_i[r4], mt);
            alpha[r4] = __expf(m_i[r4] - mnew);
            m_i[r4] = mnew;
            psum[r4] = 0.f;
        }

        // exp, partial sums, store P (tf32-rounded) into KP
        #pragma unroll
        for (int mf = 0; mf < 2; mf++) {
            #pragma unroll
            for (int nf = 0; nf < 4; nf++) {
                #pragma unroll
                for (int e = 0; e < 4; e++) {
                    int r4 = mf * 2 + (e >> 1);
                    float p = __expf(c[mf][nf][e] - m_i[r4]);
                    psum[r4] += p;
                    c[mf][nf][e] = f2tf32f(p);
                }
                float* pp = KP + (ms + 16 * mf + lr) * QP + ns + 8 * nf + 2 * lc;
                *(float2*)pp = make_float2(c[mf][nf][0], c[mf][nf][1]);
                *(float2*)(pp + 8 * QP) = make_float2(c[mf][nf][2], c[mf][nf][3]);
            }
        }
        #pragma unroll
        for (int r4 = 0; r4 < 4; r4++) {
            psum[r4] += __shfl_xor_sync(0xffffffffu, psum[r4], 1);
            psum[r4] += __shfl_xor_sync(0xffffffffu, psum[r4], 2);
        }
        if (lc == 0) {
            #pragma unroll
            for (int r4 = 0; r4 < 4; r4++)
                stSum[(ms + lr + 8 * r4) * 2 + nsi] = psum[r4];
        }
        __syncthreads();   // P fully written; sums visible

        #pragma unroll
        for (int r4 = 0; r4 < 4; r4++) {
            float so = stSum[(ms + lr + 8 * r4) * 2 + (1 - nsi)];
            l_i[r4] = l_i[r4] * alpha[r4] + psum[r4] + so;
        }
        // rescale O by alpha
        #pragma unroll
        for (int mf = 0; mf < 2; mf++)
            #pragma unroll
            for (int nf = 0; nf < 4; nf++) {
                int r40 = mf * 2, r41 = mf * 2 + 1;
                o[mf][nf][0] *= alpha[r40];
                o[mf][nf][1] *= alpha[r40];
                o[mf][nf][2] *= alpha[r41];
                o[mf][nf][3] *= alpha[r41];
            }

        // O += P V   (A = P from KP, B = V from Vs)
        #pragma unroll
        for (int ks = 0; ks < 8; ks++) {
            int kk0 = ks * 8;
            uint32_t af[2][4], bf[4][2];
            #pragma unroll
            for (int mf = 0; mf < 2; mf++) {
                const float* pp = KP + (ms + 16 * mf + lr) * QP + kk0 + lc;
                af[mf][0] = __float_as_uint(pp[0]);
                af[mf][1] = __float_as_uint(pp[8 * QP]);
                af[mf][2] = __float_as_uint(pp[4]);
                af[mf][3] = __float_as_uint(pp[8 * QP + 4]);
            }
            #pragma unroll
            for (int nf = 0; nf < 4; nf++) {
                const float* vp = Vs + (kk0 + lc) * VPIT + ns + 8 * nf + lr;
                bf[nf][0] = __float_as_uint(vp[0]);
                bf[nf][1] = __float_as_uint(vp[4 * VPIT]);
            }
            #pragma unroll
            for (int mf = 0; mf < 2; mf++)
                #pragma unroll
                for (int nf = 0; nf < 4; nf++)
                    mma_tf32(o[mf][nf], af[mf], bf[nf]);
        }
    }

    // Normalize and write back: og[(b, q0+row), h*64 + d]
    float* og = g_attn + ((size_t)b * Nn + q0) * Ee + h * Dd;
    #pragma unroll
    for (int mf = 0; mf < 2; mf++) {
        float inv0 = 1.f / l_i[mf * 2];
        float inv1 = 1.f / l_i[mf * 2 + 1];
        int r0 = ms + 16 * mf + lr;
        #pragma unroll
        for (int nf = 0; nf < 4; nf++) {
            int cc = ns + 8 * nf + 2 * lc;
            *(float2*)&og[(size_t)r0 * Ee + cc] =
                make_float2(o[mf][nf][0] * inv0, o[mf][nf][1] * inv0);
            *(float2*)&og[(size_t)(r0 + 8) * Ee + cc] =
                make_float2(o[mf][nf][2] * inv1, o[mf][nf][3] * inv1);
        }
    }
}

// ---------------------------------------------------------------------------
extern "C" void kernel_launch(void* const* d_in, const int* in_sizes, int n_in,
                              void* d_out, int out_size)
{
    const float* query = (const float*)d_in[0];
    const float* abias = (const float*)d_in[1];
    const float* Wq = (const float*)d_in[2];
    const float* bq = (const float*)d_in[3];
    const float* Wk = (const float*)d_in[4];
    const float* bk = (const float*)d_in[5];
    const float* Wv = (const float*)d_in[6];
    const float* bv = (const float*)d_in[7];
    const float* Wo = (const float*)d_in[8];
    const float* bo = (const float*)d_in[9];
    float* out = (float*)d_out;

    float* gq; cudaGetSymbolAddress((void**)&gq, g_q);
    float* gk; cudaGetSymbolAddress((void**)&gk, g_k);
    float* gv; cudaGetSymbolAddress((void**)&gv, g_v);
    float* ga; cudaGetSymbolAddress((void**)&ga, g_attn);

    cudaFuncSetAttribute(attn_mma, cudaFuncAttributeMaxDynamicSharedMemorySize, ATTN_SMEM);

    const float scaling = 0.125f;  // Dd^-0.5

    dim3 gThreads(256);
    dim3 gGridProj(Ee / BN, Mtot / BM);     // (6, 64)

    gemm_mma<<<gGridProj, gThreads>>>(query, Wq, bq, gq, Mtot, Ee, Ee, scaling);
    gemm_mma<<<gGridProj, gThreads>>>(query, Wk, bk, gk, Mtot, Ee, Ee, 1.0f);
    gemm_mma<<<gGridProj, gThreads>>>(query, Wv, bv, gv, Mtot, Ee, Ee, 1.0f);

    dim3 aGrid(Nn / 128, Hh, Bb);           // (8, 12, 8)
    attn_mma<<<aGrid, gThreads, ATTN_SMEM>>>(abias);

    gemm_mma<<<gGridProj, gThreads>>>(ga, Wo, bo, out, Mtot, Ee, Ee, 1.0f);
}